// round 11
// baseline (speedup 1.0000x reference)
#include <cuda_runtime.h>
#include <cuda_bf16.h>
#include <math.h>

// ---------------- problem dims ----------------
#define B_   64
#define S_   512
#define DIN  784
#define DEMB 600
#define DQK  64
#define DH2  200
#define DOUT 10
#define MROWS (B_*S_)   // 32768

// Eigen MT gebp K-panel size (confirmed bit-exact in R5): kc = 320
#define KC_MAIN 320

// ---------------- scratch (device globals: no allocation allowed) ----------------
__device__ unsigned int g_max_u;
static __device__ float d_spk1   [(size_t)MROWS*DEMB];
static __device__ float d_Q      [(size_t)MROWS*DQK];
static __device__ float d_K      [(size_t)MROWS*DQK];
static __device__ float d_V      [(size_t)MROWS*DEMB];
static __device__ float d_attn   [(size_t)B_*S_*S_];
static __device__ float d_attnout[(size_t)MROWS*DEMB];
static __device__ float d_spk2   [(size_t)MROWS*DH2];

// ---------------- kernels ----------------
__global__ void reset_kernel() { g_max_u = 0u; }

__global__ void reduce_max_kernel(const float* __restrict__ x, int n) {
    float m = 0.f;
    for (int i = blockIdx.x * blockDim.x + threadIdx.x; i < n; i += gridDim.x * blockDim.x)
        m = fmaxf(m, x[i]);
    #pragma unroll
    for (int o = 16; o; o >>= 1) m = fmaxf(m, __shfl_xor_sync(0xffffffffu, m, o));
    if ((threadIdx.x & 31) == 0) atomicMax(&g_max_u, __float_as_uint(m)); // x >= 0
}

// Tiled fp32 GEMM emulating Eigen gebp accumulation order (BIT-EXACT vs R5/R9):
//   per output: ascending-k fmaf chain (accP registers), folded into running
//   totals in SMEM (accTs) at kc panel boundaries (last panel = remainder).
//   512 threads / 4x4 per-thread tile: ~50 regs -> 2 blocks x 16 warps = 32
//   warps/SM (8/SMSP) vs R9's 21% occupancy. Same FFMA count; more latency
//   hiding for the fma pipe (measured 33% busy at a 2.47ms FFMA floor).
//   A: [M,K] row-major; B: b_kn==0 -> [N,K], b_kn==1 -> [K,N]
//   batched via blockIdx.z with strides sA,sB,sC (res uses sC).
//   qk2 mode: blockIdx.z==1 switches to (Bm2, bias2, C2) — fuses the Q and K
//   projections (identical A) into one launch.
// Requires: M % 128 == 0, K % 8 == 0 (true for every call site).
#define BM 128
#define BN 64
#define BK 8
#define NT 512
__global__ __launch_bounds__(NT, 2)
void gemm_kernel(const float* __restrict__ A,
                 const float* __restrict__ Bm,
                 const float* __restrict__ bias,
                 const float* __restrict__ res,
                 float* __restrict__ C,
                 const float* __restrict__ Bm2,
                 const float* __restrict__ bias2,
                 float* __restrict__ C2,
                 int qk2,
                 int M, int N, int K, int kc,
                 long long sA, long long sB, long long sC,
                 float alpha, int b_kn, int spike, float thr, int scaleA)
{
    __shared__ float As[2][BK][BM];          // 8 KB
    __shared__ float Bs[2][BK][BN];          // 4 KB
    __shared__ float accTs[16][NT];          // 32 KB; one column per thread

    long long bz = blockIdx.z;
    if (qk2 && bz == 1) { Bm = Bm2; bias = bias2; C = C2; }
    else {
        A  += bz * sA;
        Bm += bz * sB;
        C  += bz * sC;
        if (res) res += bz * sC;
    }

    const int rowBase = blockIdx.y * BM;
    const int colBase = blockIdx.x * BN;
    const int t  = threadIdx.x;              // 512 threads
    const int tx = t & 15;                   // 16 col-groups of 4
    const int ty = t >> 4;                   // 32 row-groups of 4

    float sc = 1.0f;
    if (scaleA) sc = (__uint_as_float(g_max_u) > 1.0f) ? (1.0f / 255.0f) : 1.0f;

    // ---- staging indices ----
    const int am = t >> 2;                   // A: float2 at (m=t>>2, k=(t&3)*2)
    const int ak = (t & 3) * 2;
    const int bnA = t >> 3;                  // B [N,K]: 1 float at (n=t>>3, k=t&7)
    const int bkA = t & 7;
    const int bkB = t >> 6;                  // B [K,N]: 1 float at (k=t>>6, n=t&63)
    const int bnB = t & 63;

    float2 aReg;
    float  bReg;

    auto loadA = [&](int k0) {
        aReg = *reinterpret_cast<const float2*>(A + (long long)(rowBase + am) * K + (k0 + ak));
        aReg.x *= sc; aReg.y *= sc;
    };
    auto loadB = [&](int k0) {
        if (b_kn == 0) {
            int gn = colBase + bnA;
            bReg = (gn < N) ? Bm[(long long)gn * K + (k0 + bkA)] : 0.f;
        } else {
            int gn = colBase + bnB;
            bReg = (gn < N) ? Bm[(long long)(k0 + bkB) * N + gn] : 0.f;
        }
    };
    auto storeTile = [&](int buf) {
        As[buf][ak + 0][am] = aReg.x;
        As[buf][ak + 1][am] = aReg.y;
        if (b_kn == 0) Bs[buf][bkA][bnA] = bReg;
        else           Bs[buf][bkB][bnB] = bReg;
    };

    // zero my accT column (each thread touches only its own column)
    #pragma unroll
    for (int s = 0; s < 16; s++) accTs[s][t] = 0.f;

    float accP[4][4] = {};   // current panel chains (hot registers)

    loadA(0); loadB(0);
    storeTile(0);
    __syncthreads();

    int cur = 0;
    for (int k0 = 0; k0 < K; k0 += BK) {
        const bool hasNext = (k0 + BK) < K;
        if (hasNext) { loadA(k0 + BK); loadB(k0 + BK); }

        #pragma unroll
        for (int k = 0; k < BK; k++) {       // ascending k within panel
            float4 a = *reinterpret_cast<const float4*>(&As[cur][k][ty * 4]);
            float4 b = *reinterpret_cast<const float4*>(&Bs[cur][k][tx * 4]);
            float a_[4] = {a.x, a.y, a.z, a.w};
            float b_[4] = {b.x, b.y, b.z, b.w};
            #pragma unroll
            for (int i = 0; i < 4; i++)
                #pragma unroll
                for (int j = 0; j < 4; j++)
                    accP[i][j] = fmaf(a_[i], b_[j], accP[i][j]);
        }

        // Eigen kc-panel boundary: fold panel chain into smem totals, restart.
        if ((((k0 + BK) % kc) == 0) || !hasNext) {
            #pragma unroll
            for (int i = 0; i < 4; i++)
                #pragma unroll
                for (int j = 0; j < 4; j++) {
                    accTs[i * 4 + j][t] += accP[i][j];   // scalar IEEE add, same order
                    accP[i][j] = 0.f;
                }
        }

        if (hasNext) storeTile(cur ^ 1);
        __syncthreads();
        cur ^= 1;
    }

    #pragma unroll
    for (int i = 0; i < 4; i++) {
        int gr = rowBase + ty * 4 + i;       // M % 128 == 0 -> always valid
        #pragma unroll
        for (int j = 0; j < 4; j++) {
            int gn = colBase + tx * 4 + j;
            if (gn >= N) continue;
            float v = alpha * accTs[i * 4 + j][t];  // alpha = 1.0 or 0.125 (exact)
            if (bias) v += bias[gn];
            if (res)  v += res[(long long)gr * N + gn];
            if (spike) v = (v > thr) ? 1.0f : 0.0f;
            C[(long long)gr * N + gn] = v;
        }
    }
}

// row softmax over 512 columns; one block (256 threads) per row.
__global__ __launch_bounds__(256)
void softmax512_kernel(float* __restrict__ attn)
{
    long long row = blockIdx.x;
    float* p = attn + row * (long long)S_;
    int t = threadIdx.x;
    float v0 = p[t], v1 = p[t + 256];

    __shared__ float  redf[8];
    __shared__ double redd[8];

    float m = fmaxf(v0, v1);
    #pragma unroll
    for (int o = 16; o; o >>= 1) m = fmaxf(m, __shfl_xor_sync(0xffffffffu, m, o));
    if ((t & 31) == 0) redf[t >> 5] = m;
    __syncthreads();
    float mm = redf[0];
    #pragma unroll
    for (int i = 1; i < 8; i++) mm = fmaxf(mm, redf[i]);
    __syncthreads();

    float e0 = (float)exp((double)(v0 - mm));
    float e1 = (float)exp((double)(v1 - mm));

    double s = (double)e0 + (double)e1;
    #pragma unroll
    for (int o = 16; o; o >>= 1) s += __shfl_xor_sync(0xffffffffu, s, o);
    if ((t & 31) == 0) redd[t >> 5] = s;
    __syncthreads();
    double stot_d = 0.0;
    #pragma unroll
    for (int i = 0; i < 8; i++) stot_d += redd[i];
    float stot = (float)stot_d;

    p[t]       = e0 / stot;   // IEEE fp32 divide
    p[t + 256] = e1 / stot;
}

// final layer: cur3 = spk2 @ W3^T (K=200 < 320: single panel, ascending chain),
// + b3 last; spk3 = cur3>0.3; mem3 = cur3 - 0.3*spk3
__global__ __launch_bounds__(64)
void final_kernel(const float* __restrict__ spk2,
                  const float* __restrict__ W3,
                  const float* __restrict__ b3,
                  float* __restrict__ out)
{
    int r = blockIdx.x;
    __shared__ float row[DH2];
    for (int i = threadIdx.x; i < DH2; i += blockDim.x)
        row[i] = spk2[(long long)r * DH2 + i];
    __syncthreads();
    if (threadIdx.x < DOUT) {
        int o = threadIdx.x;
        float acc = 0.0f;
        for (int k = 0; k < DH2; k++)
            acc = fmaf(row[k], W3[o * DH2 + k], acc);
        acc += b3[o];
        float spk = (acc > 0.3f) ? 1.0f : 0.0f;
        out[(long long)r * DOUT + o] = spk;
        out[(long long)MROWS * DOUT + (long long)r * DOUT + o] = acc - spk * 0.3f;
    }
}

// ---------------- launch ----------------
extern "C" void kernel_launch(void* const* d_in, const int* in_sizes, int n_in,
                              void* d_out, int out_size)
{
    const float* x  = (const float*)d_in[0];
    const float* We = (const float*)d_in[1];
    const float* be = (const float*)d_in[2];
    const float* Wq = (const float*)d_in[3];
    const float* bq = (const float*)d_in[4];
    const float* Wk = (const float*)d_in[5];
    const float* bk = (const float*)d_in[6];
    const float* Wv = (const float*)d_in[7];
    const float* bv = (const float*)d_in[8];
    const float* W2 = (const float*)d_in[9];
    const float* b2 = (const float*)d_in[10];
    const float* W3 = (const float*)d_in[11];
    const float* b3 = (const float*)d_in[12];
    float* out = (float*)d_out;

    float *spk1, *Qb, *Kb, *Vb, *attn, *attnout, *spk2;
    cudaGetSymbolAddress((void**)&spk1,    d_spk1);
    cudaGetSymbolAddress((void**)&Qb,      d_Q);
    cudaGetSymbolAddress((void**)&Kb,      d_K);
    cudaGetSymbolAddress((void**)&Vb,      d_V);
    cudaGetSymbolAddress((void**)&attn,    d_attn);
    cudaGetSymbolAddress((void**)&attnout, d_attnout);
    cudaGetSymbolAddress((void**)&spk2,    d_spk2);

    // 1) global max of x (for the /255 branch)
    reset_kernel<<<1, 1>>>();
    reduce_max_kernel<<<512, 256>>>(x, MROWS * DIN);

    // 2) embed + LIF1 -> spk1 (K=784: panels 320,320,144)
    gemm_kernel<<<dim3((DEMB + BN - 1) / BN, MROWS / BM, 1), NT>>>(
        x, We, be, nullptr, spk1, nullptr, nullptr, nullptr, 0,
        MROWS, DEMB, DIN, KC_MAIN,
        0, 0, 0, 1.0f, 0, 1, 0.5f, 1);

    // 3) Q and K fused (z=0 -> Q, z=1 -> K); K=600: panels 320,280
    gemm_kernel<<<dim3(1, MROWS / BM, 2), NT>>>(
        spk1, Wq, bq, nullptr, Qb, Wk, bk, Kb, 1,
        MROWS, DQK, DEMB, KC_MAIN,
        0, 0, 0, 1.0f, 0, 0, 0.f, 0);

    //    V (K=600: panels 320,280)
    gemm_kernel<<<dim3((DEMB + BN - 1) / BN, MROWS / BM, 1), NT>>>(
        spk1, Wv, bv, nullptr, Vb, nullptr, nullptr, nullptr, 0,
        MROWS, DEMB, DEMB, KC_MAIN,
        0, 0, 0, 1.0f, 0, 0, 0.f, 0);

    // 4) scores = Q @ K^T * 1/8 (K=64: single panel)
    gemm_kernel<<<dim3(S_ / BN, S_ / BM, B_), NT>>>(
        Qb, Kb, nullptr, nullptr, attn, nullptr, nullptr, nullptr, 0,
        S_, S_, DQK, KC_MAIN,
        (long long)S_ * DQK, (long long)S_ * DQK, (long long)S_ * S_,
        0.125f, 0, 0, 0.f, 0);

    // 5) softmax rows
    softmax512_kernel<<<B_ * S_, 256>>>(attn);

    // 6) attn_out = attn @ V + spk1 (K=512: panels 320,192); V is [K,N] per batch
    gemm_kernel<<<dim3((DEMB + BN - 1) / BN, S_ / BM, B_), NT>>>(
        attn, Vb, nullptr, spk1, attnout, nullptr, nullptr, nullptr, 0,
        S_, DEMB, S_, KC_MAIN,
        (long long)S_ * S_, (long long)S_ * DEMB, (long long)S_ * DEMB,
        1.0f, 1, 0, 0.f, 0);

    // 7) cur2 + LIF2 -> spk2 (K=600: panels 320,280)
    gemm_kernel<<<dim3((DH2 + BN - 1) / BN, MROWS / BM, 1), NT>>>(
        attnout, W2, b2, nullptr, spk2, nullptr, nullptr, nullptr, 0,
        MROWS, DH2, DEMB, KC_MAIN,
        0, 0, 0, 1.0f, 0, 1, 0.3f, 0);

    // 8) final layer -> (spk3, mem3)
    final_kernel<<<MROWS, 64>>>(spk2, W3, b3, out);

    (void)in_sizes; (void)n_in; (void)out_size;
}

// round 12
// speedup vs baseline: 1.0607x; 1.0607x over previous
#include <cuda_runtime.h>
#include <cuda_bf16.h>
#include <math.h>

// ---------------- problem dims ----------------
#define B_   64
#define S_   512
#define DIN  784
#define DEMB 600
#define DQK  64
#define DH2  200
#define DOUT 10
#define MROWS (B_*S_)   // 32768

// Eigen MT gebp K-panel size (confirmed bit-exact in R5): kc = 320
#define KC_MAIN 320

// ---------------- scratch (device globals: no allocation allowed) ----------------
__device__ unsigned int g_max_u;
static __device__ float d_spk1   [(size_t)MROWS*DEMB];
static __device__ float d_Q      [(size_t)MROWS*DQK];
static __device__ float d_K      [(size_t)MROWS*DQK];
static __device__ float d_V      [(size_t)MROWS*DEMB];
static __device__ float d_attn   [(size_t)B_*S_*S_];
static __device__ float d_attnout[(size_t)MROWS*DEMB];
static __device__ float d_spk2   [(size_t)MROWS*DH2];

// ---------------- kernels ----------------
__global__ void reset_kernel() { g_max_u = 0u; }

__global__ void reduce_max_kernel(const float* __restrict__ x, int n) {
    float m = 0.f;
    for (int i = blockIdx.x * blockDim.x + threadIdx.x; i < n; i += gridDim.x * blockDim.x)
        m = fmaxf(m, x[i]);
    #pragma unroll
    for (int o = 16; o; o >>= 1) m = fmaxf(m, __shfl_xor_sync(0xffffffffu, m, o));
    if ((threadIdx.x & 31) == 0) atomicMax(&g_max_u, __float_as_uint(m)); // x >= 0
}

// Tiled fp32 GEMM emulating Eigen gebp accumulation order (BIT-EXACT vs R5/R9):
//   per output: ascending-k fmaf chain (accP registers), folded into running
//   totals in SMEM (accTs) at kc=320 panel boundaries (last panel = remainder).
//   8x8 per-thread tile: 64 FFMA per k-step vs 4 LDS.128 -> ~91% of issued
//   instructions are FFMA (R9 was ~80% at fma pipe 33.6% of 4-slot peak; the
//   real FFMA capacity is 2/cyc/SM so ~50% = saturation).
//   A: [M,K] row-major; B: b_kn==0 -> [N,K], b_kn==1 -> [K,N]
//   batched via blockIdx.z with strides sA,sB,sC (res uses sC).
//   qk2 mode: blockIdx.z==1 switches to (Bm2, bias2, C2) — fuses Q & K projs.
// Tiling: BM=128, BN=128, BK=8, 256 threads. Dynamic smem 80KB:
//   As 2x8x128, Bs 2x8x128, accTs 64x256.
// Requires: M % 128 == 0, K % 8 == 0 (true for every call site).
#define BM 128
#define BN 128
#define BK 8
#define NT 256
#define GEMM_SMEM_FLOATS (2*BK*BM + 2*BK*BN + 64*NT)   // 2048+2048+16384 = 20480
#define GEMM_SMEM_BYTES  (GEMM_SMEM_FLOATS * 4)        // 81920

__global__ __launch_bounds__(NT, 2)
void gemm_kernel(const float* __restrict__ A,
                 const float* __restrict__ Bm,
                 const float* __restrict__ bias,
                 const float* __restrict__ res,
                 float* __restrict__ C,
                 const float* __restrict__ Bm2,
                 const float* __restrict__ bias2,
                 float* __restrict__ C2,
                 int qk2,
                 int M, int N, int K, int kc,
                 long long sA, long long sB, long long sC,
                 float alpha, int b_kn, int spike, float thr, int scaleA)
{
    extern __shared__ float smemBuf[];
    float* As_   = smemBuf;                 // [2][BK][BM]
    float* Bs_   = smemBuf + 2 * BK * BM;   // [2][BK][BN]
    float* accT_ = Bs_ + 2 * BK * BN;       // [64][NT]

    long long bz = blockIdx.z;
    if (qk2 && bz == 1) { Bm = Bm2; bias = bias2; C = C2; }
    else {
        A  += bz * sA;
        Bm += bz * sB;
        C  += bz * sC;
        if (res) res += bz * sC;
    }

    const int rowBase = blockIdx.y * BM;
    const int colBase = blockIdx.x * BN;
    const int t  = threadIdx.x;              // 256 threads
    const int tx = t & 15;                   // 16 col-groups of 8
    const int ty = t >> 4;                   // 16 row-groups of 8

    float sc = 1.0f;
    if (scaleA) sc = (__uint_as_float(g_max_u) > 1.0f) ? (1.0f / 255.0f) : 1.0f;

    // ---- staging indices ----
    const int am = t >> 1;                   // A: float4 at (m=t>>1, k=(t&1)*4)
    const int ak = (t & 1) * 4;
    const int bn0 = t >> 1;                  // B [N,K]: float4 at (n=t>>1, k=(t&1)*4)
    const int bk0 = (t & 1) * 4;
    const int bk1 = t >> 5;                  // B [K,N]: 4 scalars at (k=t>>5, n=(t&31)*4)
    const int bn1 = (t & 31) * 4;

    float4 aReg;
    float  bR0, bR1, bR2, bR3;

    auto loadA = [&](int k0) {
        aReg = *reinterpret_cast<const float4*>(A + (long long)(rowBase + am) * K + (k0 + ak));
        aReg.x *= sc; aReg.y *= sc; aReg.z *= sc; aReg.w *= sc;
    };
    auto loadB = [&](int k0) {
        if (b_kn == 0) {
            int gn = colBase + bn0;
            if (gn < N) {
                float4 v = *reinterpret_cast<const float4*>(Bm + (long long)gn * K + (k0 + bk0));
                bR0 = v.x; bR1 = v.y; bR2 = v.z; bR3 = v.w;
            } else { bR0 = bR1 = bR2 = bR3 = 0.f; }
        } else {
            long long rowOff = (long long)(k0 + bk1) * N;
            int gn = colBase + bn1;
            bR0 = (gn     < N) ? Bm[rowOff + gn]     : 0.f;
            bR1 = (gn + 1 < N) ? Bm[rowOff + gn + 1] : 0.f;
            bR2 = (gn + 2 < N) ? Bm[rowOff + gn + 2] : 0.f;
            bR3 = (gn + 3 < N) ? Bm[rowOff + gn + 3] : 0.f;
        }
    };
    auto storeTile = [&](int buf) {
        float* Ab = As_ + buf * BK * BM;
        Ab[(ak + 0) * BM + am] = aReg.x;
        Ab[(ak + 1) * BM + am] = aReg.y;
        Ab[(ak + 2) * BM + am] = aReg.z;
        Ab[(ak + 3) * BM + am] = aReg.w;
        float* Bb = Bs_ + buf * BK * BN;
        if (b_kn == 0) {
            Bb[(bk0 + 0) * BN + bn0] = bR0;
            Bb[(bk0 + 1) * BN + bn0] = bR1;
            Bb[(bk0 + 2) * BN + bn0] = bR2;
            Bb[(bk0 + 3) * BN + bn0] = bR3;
        } else {
            Bb[bk1 * BN + bn1 + 0] = bR0;
            Bb[bk1 * BN + bn1 + 1] = bR1;
            Bb[bk1 * BN + bn1 + 2] = bR2;
            Bb[bk1 * BN + bn1 + 3] = bR3;
        }
    };

    // zero my accT column (each thread touches only its own column)
    #pragma unroll
    for (int s = 0; s < 64; s++) accT_[s * NT + t] = 0.f;

    float accP[8][8] = {};   // current panel chains (hot registers)

    loadA(0); loadB(0);
    storeTile(0);
    __syncthreads();

    int cur = 0;
    for (int k0 = 0; k0 < K; k0 += BK) {
        const bool hasNext = (k0 + BK) < K;
        if (hasNext) { loadA(k0 + BK); loadB(k0 + BK); }

        const float* Ab = As_ + cur * BK * BM;
        const float* Bb = Bs_ + cur * BK * BN;
        #pragma unroll
        for (int k = 0; k < BK; k++) {       // ascending k within panel
            float4 a0 = *reinterpret_cast<const float4*>(Ab + k * BM + ty * 8);
            float4 a1 = *reinterpret_cast<const float4*>(Ab + k * BM + ty * 8 + 4);
            float4 b0 = *reinterpret_cast<const float4*>(Bb + k * BN + tx * 8);
            float4 b1 = *reinterpret_cast<const float4*>(Bb + k * BN + tx * 8 + 4);
            float a_[8] = {a0.x, a0.y, a0.z, a0.w, a1.x, a1.y, a1.z, a1.w};
            float b_[8] = {b0.x, b0.y, b0.z, b0.w, b1.x, b1.y, b1.z, b1.w};
            #pragma unroll
            for (int i = 0; i < 8; i++)
                #pragma unroll
                for (int j = 0; j < 8; j++)
                    accP[i][j] = fmaf(a_[i], b_[j], accP[i][j]);
        }

        // Eigen kc-panel boundary: fold panel chain into smem totals, restart.
        if ((((k0 + BK) % kc) == 0) || !hasNext) {
            #pragma unroll
            for (int i = 0; i < 8; i++)
                #pragma unroll
                for (int j = 0; j < 8; j++) {
                    accT_[(i * 8 + j) * NT + t] += accP[i][j];  // scalar IEEE add
                    accP[i][j] = 0.f;
                }
        }

        if (hasNext) storeTile(cur ^ 1);
        __syncthreads();
        cur ^= 1;
    }

    #pragma unroll
    for (int i = 0; i < 8; i++) {
        int gr = rowBase + ty * 8 + i;       // M % 128 == 0 -> always valid
        #pragma unroll
        for (int j = 0; j < 8; j++) {
            int gn = colBase + tx * 8 + j;
            if (gn >= N) continue;
            float v = alpha * accT_[(i * 8 + j) * NT + t];  // alpha exact (1.0/0.125)
            if (bias) v += bias[gn];
            if (res)  v += res[(long long)gr * N + gn];
            if (spike) v = (v > thr) ? 1.0f : 0.0f;
            C[(long long)gr * N + gn] = v;
        }
    }
}

// row softmax over 512 columns; one block (256 threads) per row.
__global__ __launch_bounds__(256)
void softmax512_kernel(float* __restrict__ attn)
{
    long long row = blockIdx.x;
    float* p = attn + row * (long long)S_;
    int t = threadIdx.x;
    float v0 = p[t], v1 = p[t + 256];

    __shared__ float  redf[8];
    __shared__ double redd[8];

    float m = fmaxf(v0, v1);
    #pragma unroll
    for (int o = 16; o; o >>= 1) m = fmaxf(m, __shfl_xor_sync(0xffffffffu, m, o));
    if ((t & 31) == 0) redf[t >> 5] = m;
    __syncthreads();
    float mm = redf[0];
    #pragma unroll
    for (int i = 1; i < 8; i++) mm = fmaxf(mm, redf[i]);
    __syncthreads();

    float e0 = (float)exp((double)(v0 - mm));
    float e1 = (float)exp((double)(v1 - mm));

    double s = (double)e0 + (double)e1;
    #pragma unroll
    for (int o = 16; o; o >>= 1) s += __shfl_xor_sync(0xffffffffu, s, o);
    if ((t & 31) == 0) redd[t >> 5] = s;
    __syncthreads();
    double stot_d = 0.0;
    #pragma unroll
    for (int i = 0; i < 8; i++) stot_d += redd[i];
    float stot = (float)stot_d;

    p[t]       = e0 / stot;   // IEEE fp32 divide
    p[t + 256] = e1 / stot;
}

// final layer: cur3 = spk2 @ W3^T (K=200 < 320: single panel, ascending chain),
// + b3 last; spk3 = cur3>0.3; mem3 = cur3 - 0.3*spk3
__global__ __launch_bounds__(64)
void final_kernel(const float* __restrict__ spk2,
                  const float* __restrict__ W3,
                  const float* __restrict__ b3,
                  float* __restrict__ out)
{
    int r = blockIdx.x;
    __shared__ float row[DH2];
    for (int i = threadIdx.x; i < DH2; i += blockDim.x)
        row[i] = spk2[(long long)r * DH2 + i];
    __syncthreads();
    if (threadIdx.x < DOUT) {
        int o = threadIdx.x;
        float acc = 0.0f;
        for (int k = 0; k < DH2; k++)
            acc = fmaf(row[k], W3[o * DH2 + k], acc);
        acc += b3[o];
        float spk = (acc > 0.3f) ? 1.0f : 0.0f;
        out[(long long)r * DOUT + o] = spk;
        out[(long long)MROWS * DOUT + (long long)r * DOUT + o] = acc - spk * 0.3f;
    }
}

// ---------------- launch ----------------
extern "C" void kernel_launch(void* const* d_in, const int* in_sizes, int n_in,
                              void* d_out, int out_size)
{
    const float* x  = (const float*)d_in[0];
    const float* We = (const float*)d_in[1];
    const float* be = (const float*)d_in[2];
    const float* Wq = (const float*)d_in[3];
    const float* bq = (const float*)d_in[4];
    const float* Wk = (const float*)d_in[5];
    const float* bk = (const float*)d_in[6];
    const float* Wv = (const float*)d_in[7];
    const float* bv = (const float*)d_in[8];
    const float* W2 = (const float*)d_in[9];
    const float* b2 = (const float*)d_in[10];
    const float* W3 = (const float*)d_in[11];
    const float* b3 = (const float*)d_in[12];
    float* out = (float*)d_out;

    float *spk1, *Qb, *Kb, *Vb, *attn, *attnout, *spk2;
    cudaGetSymbolAddress((void**)&spk1,    d_spk1);
    cudaGetSymbolAddress((void**)&Qb,      d_Q);
    cudaGetSymbolAddress((void**)&Kb,      d_K);
    cudaGetSymbolAddress((void**)&Vb,      d_V);
    cudaGetSymbolAddress((void**)&attn,    d_attn);
    cudaGetSymbolAddress((void**)&attnout, d_attnout);
    cudaGetSymbolAddress((void**)&spk2,    d_spk2);

    // allow 80KB dynamic smem (idempotent; not an allocation)
    static int smemSet = 0;
    if (!smemSet) {
        cudaFuncSetAttribute(gemm_kernel,
                             cudaFuncAttributeMaxDynamicSharedMemorySize,
                             GEMM_SMEM_BYTES);
        smemSet = 1;
    }

    // 1) global max of x (for the /255 branch)
    reset_kernel<<<1, 1>>>();
    reduce_max_kernel<<<512, 256>>>(x, MROWS * DIN);

    // 2) embed + LIF1 -> spk1 (K=784: panels 320,320,144)
    gemm_kernel<<<dim3((DEMB + BN - 1) / BN, MROWS / BM, 1), NT, GEMM_SMEM_BYTES>>>(
        x, We, be, nullptr, spk1, nullptr, nullptr, nullptr, 0,
        MROWS, DEMB, DIN, KC_MAIN,
        0, 0, 0, 1.0f, 0, 1, 0.5f, 1);

    // 3) Q and K fused (z=0 -> Q, z=1 -> K); K=600: panels 320,280
    gemm_kernel<<<dim3(1, MROWS / BM, 2), NT, GEMM_SMEM_BYTES>>>(
        spk1, Wq, bq, nullptr, Qb, Wk, bk, Kb, 1,
        MROWS, DQK, DEMB, KC_MAIN,
        0, 0, 0, 1.0f, 0, 0, 0.f, 0);

    //    V (K=600: panels 320,280)
    gemm_kernel<<<dim3((DEMB + BN - 1) / BN, MROWS / BM, 1), NT, GEMM_SMEM_BYTES>>>(
        spk1, Wv, bv, nullptr, Vb, nullptr, nullptr, nullptr, 0,
        MROWS, DEMB, DEMB, KC_MAIN,
        0, 0, 0, 1.0f, 0, 0, 0.f, 0);

    // 4) scores = Q @ K^T * 1/8 (K=64: single panel)
    gemm_kernel<<<dim3(S_ / BN, S_ / BM, B_), NT, GEMM_SMEM_BYTES>>>(
        Qb, Kb, nullptr, nullptr, attn, nullptr, nullptr, nullptr, 0,
        S_, S_, DQK, KC_MAIN,
        (long long)S_ * DQK, (long long)S_ * DQK, (long long)S_ * S_,
        0.125f, 0, 0, 0.f, 0);

    // 5) softmax rows
    softmax512_kernel<<<B_ * S_, 256>>>(attn);

    // 6) attn_out = attn @ V + spk1 (K=512: panels 320,192); V is [K,N] per batch
    gemm_kernel<<<dim3((DEMB + BN - 1) / BN, S_ / BM, B_), NT, GEMM_SMEM_BYTES>>>(
        attn, Vb, nullptr, spk1, attnout, nullptr, nullptr, nullptr, 0,
        S_, DEMB, S_, KC_MAIN,
        (long long)S_ * S_, (long long)S_ * DEMB, (long long)S_ * DEMB,
        1.0f, 1, 0, 0.f, 0);

    // 7) cur2 + LIF2 -> spk2 (K=600: panels 320,280)
    gemm_kernel<<<dim3((DH2 + BN - 1) / BN, MROWS / BM, 1), NT, GEMM_SMEM_BYTES>>>(
        attnout, W2, b2, nullptr, spk2, nullptr, nullptr, nullptr, 0,
        MROWS, DH2, DEMB, KC_MAIN,
        0, 0, 0, 1.0f, 0, 1, 0.3f, 0);

    // 8) final layer -> (spk3, mem3)
    final_kernel<<<MROWS, 64>>>(spk2, W3, b3, out);

    (void)in_sizes; (void)n_in; (void)out_size;
}

// round 14
// speedup vs baseline: 1.2347x; 1.1641x over previous
#include <cuda_runtime.h>
#include <cuda_bf16.h>
#include <math.h>

// ---------------- problem dims ----------------
#define B_   64
#define S_   512
#define DIN  784
#define DEMB 600
#define DQK  64
#define DH2  200
#define DOUT 10
#define MROWS (B_*S_)   // 32768

// Eigen MT gebp K-panel size (confirmed bit-exact in R5): kc = 320
#define KC_MAIN 320

// ---------------- scratch (device globals: no allocation allowed) ----------------
__device__ unsigned int g_max_u;
static __device__ float d_spk1   [(size_t)MROWS*DEMB];
static __device__ float d_QK     [(size_t)MROWS*(2*DQK)];   // Q cols 0-63, K cols 64-127
static __device__ float d_V      [(size_t)MROWS*DEMB];
static __device__ float d_attn   [(size_t)B_*S_*S_];
static __device__ float d_attnout[(size_t)MROWS*DEMB];
static __device__ float d_spk2   [(size_t)MROWS*DH2];
static __device__ float d_Wqk    [(size_t)(2*DQK)*DEMB];    // packed Wq ; Wk
static __device__ float d_bqk    [2*DQK];

// ---------------- kernels ----------------
__global__ void reset_kernel() { g_max_u = 0u; }

__global__ void reduce_max_kernel(const float* __restrict__ x, int n) {
    float m = 0.f;
    for (int i = blockIdx.x * blockDim.x + threadIdx.x; i < n; i += gridDim.x * blockDim.x)
        m = fmaxf(m, x[i]);
    #pragma unroll
    for (int o = 16; o; o >>= 1) m = fmaxf(m, __shfl_xor_sync(0xffffffffu, m, o));
    if ((threadIdx.x & 31) == 0) atomicMax(&g_max_u, __float_as_uint(m)); // x >= 0
}

// pack Wq (64x600) and Wk (64x600) into Wqk (128x600); bq,bk -> bqk
__global__ void pack_qk_kernel(const float* __restrict__ Wq, const float* __restrict__ Wk,
                               const float* __restrict__ bq, const float* __restrict__ bk,
                               float* __restrict__ Wqk, float* __restrict__ bqk)
{
    int i = blockIdx.x * blockDim.x + threadIdx.x;
    int n = DQK * DEMB;
    if (i < n) {
        Wqk[i]     = Wq[i];
        Wqk[n + i] = Wk[i];
    }
    if (i < DQK) { bqk[i] = bq[i]; bqk[DQK + i] = bk[i]; }
}

// Tiled fp32 GEMM emulating Eigen gebp accumulation order (BIT-EXACT vs R5/R9):
//   per output: ascending-k fmaf chain (accP regs), folded into smem running
//   totals at kc=320 panel boundaries (last panel = remainder).
//   BK=16 (8-remainder path for K=600) halves the per-chunk __syncthreads
//   convoy that capped R9 at fma=33%. kc=320 is 16-aligned -> folds stay
//   chunk-aligned, chains byte-identical.
//   A: [M,*] row stride lda; B: b_kn==0 -> [N,*] stride ldb (dot rows),
//   b_kn==1 -> [*,N] stride ldb. Batched via blockIdx.z (sA,sB,sC; res uses sC).
// Tiling: BM=128, BN=64, BK=16, 256 threads, 8x4 per-thread tile, 3 blocks/SM.
// Requires: M % 128 == 0, K % 8 == 0.
#define BM 128
#define BN 64
#define BK 16
#define NT 256
__global__ __launch_bounds__(NT, 3)
void gemm_kernel(const float* __restrict__ A,
                 const float* __restrict__ Bm,
                 const float* __restrict__ bias,
                 const float* __restrict__ res,
                 float* __restrict__ C,
                 int M, int N, int K, int lda, int ldb, int kc,
                 long long sA, long long sB, long long sC,
                 float alpha, int b_kn, int spike, float thr, int scaleA)
{
    __shared__ float As[2][BK][BM];      // 16 KB
    __shared__ float Bs[2][BK][BN];      // 8 KB
    __shared__ float accTs[32][NT];      // 32 KB; one column per thread

    long long bz = blockIdx.z;
    A  += bz * sA;
    Bm += bz * sB;
    C  += bz * sC;
    if (res) res += bz * sC;

    const int rowBase = blockIdx.y * BM;
    const int colBase = blockIdx.x * BN;
    const int t  = threadIdx.x;          // 256 threads
    const int tx = t & 15;               // 16 col-groups of 4
    const int ty = t >> 4;               // 16 row-groups of 8

    float sc = 1.0f;
    if (scaleA) sc = (__uint_as_float(g_max_u) > 1.0f) ? (1.0f / 255.0f) : 1.0f;

    // ---- staging indices ----
    const int am = t >> 1;               // A: 2x float4 at (m=t>>1, k=(t&1)*4 and +8)
    const int ak = (t & 1) * 4;
    const int bn0 = t >> 2;              // B [N,*]: float4 at (n=t>>2, k=(t&3)*4)
    const int bk0 = (t & 3) * 4;
    const int bk1 = t >> 4;              // B [*,N]: 4 scalars at (k=t>>4, n=(t&15)*4)
    const int bn1 = (t & 15) * 4;

    float4 aR0, aR1;
    float  bR0, bR1, bR2, bR3;

    auto loadA = [&](int k0) {
        const float* base = A + (long long)(rowBase + am) * lda;
        if (k0 + ak < K) {
            aR0 = *reinterpret_cast<const float4*>(base + k0 + ak);
            aR0.x *= sc; aR0.y *= sc; aR0.z *= sc; aR0.w *= sc;
        } else aR0 = make_float4(0.f, 0.f, 0.f, 0.f);
        if (k0 + 8 + ak < K) {
            aR1 = *reinterpret_cast<const float4*>(base + k0 + 8 + ak);
            aR1.x *= sc; aR1.y *= sc; aR1.z *= sc; aR1.w *= sc;
        } else aR1 = make_float4(0.f, 0.f, 0.f, 0.f);
    };
    auto loadB = [&](int k0) {
        if (b_kn == 0) {
            int gn = colBase + bn0;
            if (gn < N && (k0 + bk0) < K) {
                float4 v = *reinterpret_cast<const float4*>(Bm + (long long)gn * ldb + (k0 + bk0));
                bR0 = v.x; bR1 = v.y; bR2 = v.z; bR3 = v.w;
            } else { bR0 = bR1 = bR2 = bR3 = 0.f; }
        } else {
            int gk = k0 + bk1;
            int gn = colBase + bn1;
            if (gk < K) {
                long long ro = (long long)gk * ldb;
                bR0 = (gn     < N) ? Bm[ro + gn]     : 0.f;
                bR1 = (gn + 1 < N) ? Bm[ro + gn + 1] : 0.f;
                bR2 = (gn + 2 < N) ? Bm[ro + gn + 2] : 0.f;
                bR3 = (gn + 3 < N) ? Bm[ro + gn + 3] : 0.f;
            } else { bR0 = bR1 = bR2 = bR3 = 0.f; }
        }
    };
    auto storeTile = [&](int buf) {
        As[buf][ak + 0][am] = aR0.x;
        As[buf][ak + 1][am] = aR0.y;
        As[buf][ak + 2][am] = aR0.z;
        As[buf][ak + 3][am] = aR0.w;
        As[buf][ak + 8][am]  = aR1.x;
        As[buf][ak + 9][am]  = aR1.y;
        As[buf][ak + 10][am] = aR1.z;
        As[buf][ak + 11][am] = aR1.w;
        if (b_kn == 0) {
            Bs[buf][bk0 + 0][bn0] = bR0;
            Bs[buf][bk0 + 1][bn0] = bR1;
            Bs[buf][bk0 + 2][bn0] = bR2;
            Bs[buf][bk0 + 3][bn0] = bR3;
        } else {
            Bs[buf][bk1][bn1 + 0] = bR0;
            Bs[buf][bk1][bn1 + 1] = bR1;
            Bs[buf][bk1][bn1 + 2] = bR2;
            Bs[buf][bk1][bn1 + 3] = bR3;
        }
    };

    // zero my accT column (each thread touches only its own column)
    #pragma unroll
    for (int s = 0; s < 32; s++) accTs[s][t] = 0.f;

    float accP[8][4] = {};   // current panel chains (hot registers)

    loadA(0); loadB(0);
    storeTile(0);
    __syncthreads();

    int cur = 0;
    int k0 = 0;
    while (k0 < K) {
        const int cs = (K - k0 < BK) ? (K - k0) : BK;   // 16, or 8 remainder
        const int kn = k0 + cs;
        const bool hasNext = kn < K;
        if (hasNext) { loadA(kn); loadB(kn); }

        // ascending k within panel; cs is 16 or 8
        #define KSTEP(kk)                                                        \
        {                                                                        \
            float4 a0 = *reinterpret_cast<const float4*>(&As[cur][kk][ty * 8]);  \
            float4 a1 = *reinterpret_cast<const float4*>(&As[cur][kk][ty * 8 + 4]);\
            float4 b  = *reinterpret_cast<const float4*>(&Bs[cur][kk][tx * 4]);  \
            float a_[8] = {a0.x, a0.y, a0.z, a0.w, a1.x, a1.y, a1.z, a1.w};      \
            float b_[4] = {b.x, b.y, b.z, b.w};                                  \
            _Pragma("unroll")                                                    \
            for (int i = 0; i < 8; i++)                                          \
                _Pragma("unroll")                                                \
                for (int j = 0; j < 4; j++)                                      \
                    accP[i][j] = fmaf(a_[i], b_[j], accP[i][j]);                 \
        }
        if (cs == BK) {
            #pragma unroll
            for (int k = 0; k < BK; k++) KSTEP(k)
        } else {
            #pragma unroll
            for (int k = 0; k < 8; k++) KSTEP(k)
        }
        #undef KSTEP

        // Eigen kc-panel boundary (kc % 16 == 0 -> always chunk-aligned)
        if (((kn % kc) == 0) || !hasNext) {
            #pragma unroll
            for (int i = 0; i < 8; i++)
                #pragma unroll
                for (int j = 0; j < 4; j++) {
                    accTs[i * 4 + j][t] += accP[i][j];   // scalar IEEE add, same order
                    accP[i][j] = 0.f;
                }
        }

        if (hasNext) storeTile(cur ^ 1);
        __syncthreads();
        cur ^= 1;
        k0 = kn;
    }

    #pragma unroll
    for (int i = 0; i < 8; i++) {
        int gr = rowBase + ty * 8 + i;   // M % 128 == 0 -> always valid
        #pragma unroll
        for (int j = 0; j < 4; j++) {
            int gn = colBase + tx * 4 + j;
            if (gn >= N) continue;
            float v = alpha * accTs[i * 4 + j][t];  // alpha = 1.0 or 0.125 (exact)
            if (bias) v += bias[gn];
            if (res)  v += res[(long long)gr * N + gn];
            if (spike) v = (v > thr) ? 1.0f : 0.0f;
            C[(long long)gr * N + gn] = v;
        }
    }
}

// row softmax over 512 columns; one block (256 threads) per row.
__global__ __launch_bounds__(256)
void softmax512_kernel(float* __restrict__ attn)
{
    long long row = blockIdx.x;
    float* p = attn + row * (long long)S_;
    int t = threadIdx.x;
    float v0 = p[t], v1 = p[t + 256];

    __shared__ float  redf[8];
    __shared__ double redd[8];

    float m = fmaxf(v0, v1);
    #pragma unroll
    for (int o = 16; o; o >>= 1) m = fmaxf(m, __shfl_xor_sync(0xffffffffu, m, o));
    if ((t & 31) == 0) redf[t >> 5] = m;
    __syncthreads();
    float mm = redf[0];
    #pragma unroll
    for (int i = 1; i < 8; i++) mm = fmaxf(mm, redf[i]);
    __syncthreads();

    float e0 = (float)exp((double)(v0 - mm));
    float e1 = (float)exp((double)(v1 - mm));

    double s = (double)e0 + (double)e1;
    #pragma unroll
    for (int o = 16; o; o >>= 1) s += __shfl_xor_sync(0xffffffffu, s, o);
    if ((t & 31) == 0) redd[t >> 5] = s;
    __syncthreads();
    double stot_d = 0.0;
    #pragma unroll
    for (int i = 0; i < 8; i++) stot_d += redd[i];
    float stot = (float)stot_d;

    p[t]       = e0 / stot;   // IEEE fp32 divide
    p[t + 256] = e1 / stot;
}

// final layer: cur3 = spk2 @ W3^T (K=200 < 320: single panel, ascending chain),
// + b3 last; spk3 = cur3>0.3; mem3 = cur3 - 0.3*spk3
__global__ __launch_bounds__(64)
void final_kernel(const float* __restrict__ spk2,
                  const float* __restrict__ W3,
                  const float* __restrict__ b3,
                  float* __restrict__ out)
{
    int r = blockIdx.x;
    __shared__ float row[DH2];
    for (int i = threadIdx.x; i < DH2; i += blockDim.x)
        row[i] = spk2[(long long)r * DH2 + i];
    __syncthreads();
    if (threadIdx.x < DOUT) {
        int o = threadIdx.x;
        float acc = 0.0f;
        for (int k = 0; k < DH2; k++)
            acc = fmaf(row[k], W3[o * DH2 + k], acc);
        acc += b3[o];
        float spk = (acc > 0.3f) ? 1.0f : 0.0f;
        out[(long long)r * DOUT + o] = spk;
        out[(long long)MROWS * DOUT + (long long)r * DOUT + o] = acc - spk * 0.3f;
    }
}

// ---------------- launch ----------------
extern "C" void kernel_launch(void* const* d_in, const int* in_sizes, int n_in,
                              void* d_out, int out_size)
{
    const float* x  = (const float*)d_in[0];
    const float* We = (const float*)d_in[1];
    const float* be = (const float*)d_in[2];
    const float* Wq = (const float*)d_in[3];
    const float* bq = (const float*)d_in[4];
    const float* Wk = (const float*)d_in[5];
    const float* bk = (const float*)d_in[6];
    const float* Wv = (const float*)d_in[7];
    const float* bv = (const float*)d_in[8];
    const float* W2 = (const float*)d_in[9];
    const float* b2 = (const float*)d_in[10];
    const float* W3 = (const float*)d_in[11];
    const float* b3 = (const float*)d_in[12];
    float* out = (float*)d_out;

    float *spk1, *QKb, *Vb, *attn, *attnout, *spk2, *Wqk, *bqk;
    cudaGetSymbolAddress((void**)&spk1,    d_spk1);
    cudaGetSymbolAddress((void**)&QKb,     d_QK);
    cudaGetSymbolAddress((void**)&Vb,      d_V);
    cudaGetSymbolAddress((void**)&attn,    d_attn);
    cudaGetSymbolAddress((void**)&attnout, d_attnout);
    cudaGetSymbolAddress((void**)&spk2,    d_spk2);
    cudaGetSymbolAddress((void**)&Wqk,     d_Wqk);
    cudaGetSymbolAddress((void**)&bqk,     d_bqk);

    // 1) global max of x; pack Wq|Wk
    reset_kernel<<<1, 1>>>();
    reduce_max_kernel<<<512, 256>>>(x, MROWS * DIN);
    pack_qk_kernel<<<(DQK * DEMB + 255) / 256, 256>>>(Wq, Wk, bq, bk, Wqk, bqk);

    // 2) embed + LIF1 -> spk1 (K=784: panels 320,320,144)
    gemm_kernel<<<dim3((DEMB + BN - 1) / BN, MROWS / BM, 1), NT>>>(
        x, We, be, nullptr, spk1,
        MROWS, DEMB, DIN, DIN, DIN, KC_MAIN,
        0, 0, 0, 1.0f, 0, 1, 0.5f, 1);

    // 3) QK fused (N=128, packed weights) -> QK[32768,128]; K=600: panels 320,280
    gemm_kernel<<<dim3(2 * DQK / BN, MROWS / BM, 1), NT>>>(
        spk1, Wqk, bqk, nullptr, QKb,
        MROWS, 2 * DQK, DEMB, DEMB, DEMB, KC_MAIN,
        0, 0, 0, 1.0f, 0, 0, 0.f, 0);

    //    V (K=600: panels 320,280)
    gemm_kernel<<<dim3((DEMB + BN - 1) / BN, MROWS / BM, 1), NT>>>(
        spk1, Wv, bv, nullptr, Vb,
        MROWS, DEMB, DEMB, DEMB, DEMB, KC_MAIN,
        0, 0, 0, 1.0f, 0, 0, 0.f, 0);

    // 4) scores = Q @ K^T * 1/8 (K=64: single panel); Q,K strided in QK (ld=128)
    gemm_kernel<<<dim3(S_ / BN, S_ / BM, B_), NT>>>(
        QKb, QKb + DQK, nullptr, nullptr, attn,
        S_, S_, DQK, 2 * DQK, 2 * DQK, KC_MAIN,
        (long long)S_ * 2 * DQK, (long long)S_ * 2 * DQK, (long long)S_ * S_,
        0.125f, 0, 0, 0.f, 0);

    // 5) softmax rows
    softmax512_kernel<<<B_ * S_, 256>>>(attn);

    // 6) attn_out = attn @ V + spk1 (K=512: panels 320,192); V is [K,N] per batch
    gemm_kernel<<<dim3((DEMB + BN - 1) / BN, S_ / BM, B_), NT>>>(
        attn, Vb, nullptr, spk1, attnout,
        S_, DEMB, S_, S_, DEMB, KC_MAIN,
        (long long)S_ * S_, (long long)S_ * DEMB, (long long)S_ * DEMB,
        1.0f, 1, 0, 0.f, 0);

    // 7) cur2 + LIF2 -> spk2 (K=600: panels 320,280)
    gemm_kernel<<<dim3((DH2 + BN - 1) / BN, MROWS / BM, 1), NT>>>(
        attnout, W2, b2, nullptr, spk2,
        MROWS, DH2, DEMB, DEMB, DEMB, KC_MAIN,
        0, 0, 0, 1.0f, 0, 1, 0.3f, 0);

    // 8) final layer -> (spk3, mem3)
    final_kernel<<<MROWS, 64>>>(spk2, W3, b3, out);

    (void)in_sizes; (void)n_in; (void)out_size;
}

// round 15
// speedup vs baseline: 1.2640x; 1.0237x over previous
#include <cuda_runtime.h>
#include <cuda_bf16.h>
#include <math.h>

// ---------------- problem dims ----------------
#define B_   64
#define S_   512
#define DIN  784
#define DEMB 600
#define DQK  64
#define DH2  200
#define DOUT 10
#define MROWS (B_*S_)   // 32768

// Eigen MT gebp K-panel size (confirmed bit-exact in R5): kc = 320
#define KC_MAIN 320

// ---------------- scratch (device globals: no allocation allowed) ----------------
__device__ unsigned int g_max_u;
static __device__ float d_spk1   [(size_t)MROWS*DEMB];
static __device__ float d_QK     [(size_t)MROWS*(2*DQK)];   // Q cols 0-63, K cols 64-127
static __device__ float d_V      [(size_t)MROWS*DEMB];
static __device__ float d_attn   [(size_t)B_*S_*S_];
static __device__ float d_attnout[(size_t)MROWS*DEMB];
static __device__ float d_spk2   [(size_t)MROWS*DH2];
static __device__ float d_Wqk    [(size_t)(2*DQK)*DEMB];    // packed Wq ; Wk
static __device__ float d_bqk    [2*DQK];

// ---------------- kernels ----------------
__global__ void reset_kernel() { g_max_u = 0u; }

__global__ void reduce_max_kernel(const float* __restrict__ x, int n) {
    float m = 0.f;
    for (int i = blockIdx.x * blockDim.x + threadIdx.x; i < n; i += gridDim.x * blockDim.x)
        m = fmaxf(m, x[i]);
    #pragma unroll
    for (int o = 16; o; o >>= 1) m = fmaxf(m, __shfl_xor_sync(0xffffffffu, m, o));
    if ((threadIdx.x & 31) == 0) atomicMax(&g_max_u, __float_as_uint(m)); // x >= 0
}

// pack Wq (64x600) and Wk (64x600) into Wqk (128x600); bq,bk -> bqk
__global__ void pack_qk_kernel(const float* __restrict__ Wq, const float* __restrict__ Wk,
                               const float* __restrict__ bq, const float* __restrict__ bk,
                               float* __restrict__ Wqk, float* __restrict__ bqk)
{
    int i = blockIdx.x * blockDim.x + threadIdx.x;
    int n = DQK * DEMB;
    if (i < n) {
        Wqk[i]     = Wq[i];
        Wqk[n + i] = Wk[i];
    }
    if (i < DQK) { bqk[i] = bq[i]; bqk[DQK + i] = bk[i]; }
}

// Tiled fp32 GEMM emulating Eigen gebp accumulation order (BIT-EXACT vs R5/R14):
//   per output: ascending-k fmaf chain (accP regs), folded into smem running
//   totals at kc=320 panel boundaries (last panel = remainder).
//   SP=true: single-panel specialization (K <= kc): totals stay in accP regs,
//   accTs machinery removed entirely (bitwise identical: R14's fold was 0+accP).
//   A: [M,*] row stride lda; B: b_kn==0 -> [N,*] stride ldb (dot rows),
//   b_kn==1 -> [*,N] stride ldb. Batched via blockIdx.z (sA,sB,sC; res uses sC).
// Tiling: BM=128, BN=64, BK=16 (8-remainder path), 256 threads, 8x4 tile.
// Requires: M % 128 == 0, K % 8 == 0.
#define BM 128
#define BN 64
#define BK 16
#define NT 256
template<bool SP>
__global__ __launch_bounds__(NT, 3)
void gemm_kernel(const float* __restrict__ A,
                 const float* __restrict__ Bm,
                 const float* __restrict__ bias,
                 const float* __restrict__ res,
                 float* __restrict__ C,
                 int M, int N, int K, int lda, int ldb, int kc,
                 long long sA, long long sB, long long sC,
                 float alpha, int b_kn, int spike, float thr, int scaleA)
{
    __shared__ float As[2][BK][BM];      // 16 KB
    __shared__ float Bs[2][BK][BN];      // 8 KB
    __shared__ float accTs[SP ? 1 : 32][NT];  // 32 KB (1 KB unused when SP)

    long long bz = blockIdx.z;
    A  += bz * sA;
    Bm += bz * sB;
    C  += bz * sC;
    if (res) res += bz * sC;

    const int rowBase = blockIdx.y * BM;
    const int colBase = blockIdx.x * BN;
    const int t  = threadIdx.x;          // 256 threads
    const int tx = t & 15;               // 16 col-groups of 4
    const int ty = t >> 4;               // 16 row-groups of 8

    float sc = 1.0f;
    if (scaleA) sc = (__uint_as_float(g_max_u) > 1.0f) ? (1.0f / 255.0f) : 1.0f;

    // ---- staging indices ----
    const int am = t >> 1;               // A: 2x float4 at (m=t>>1, k=(t&1)*4 and +8)
    const int ak = (t & 1) * 4;
    const int bn0 = t >> 2;              // B [N,*]: float4 at (n=t>>2, k=(t&3)*4)
    const int bk0 = (t & 3) * 4;
    const int bk1 = t >> 4;              // B [*,N]: 4 scalars at (k=t>>4, n=(t&15)*4)
    const int bn1 = (t & 15) * 4;

    float4 aR0, aR1;
    float  bR0, bR1, bR2, bR3;

    auto loadA = [&](int k0) {
        const float* base = A + (long long)(rowBase + am) * lda;
        if (k0 + ak < K) {
            aR0 = *reinterpret_cast<const float4*>(base + k0 + ak);
            aR0.x *= sc; aR0.y *= sc; aR0.z *= sc; aR0.w *= sc;
        } else aR0 = make_float4(0.f, 0.f, 0.f, 0.f);
        if (k0 + 8 + ak < K) {
            aR1 = *reinterpret_cast<const float4*>(base + k0 + 8 + ak);
            aR1.x *= sc; aR1.y *= sc; aR1.z *= sc; aR1.w *= sc;
        } else aR1 = make_float4(0.f, 0.f, 0.f, 0.f);
    };
    auto loadB = [&](int k0) {
        if (b_kn == 0) {
            int gn = colBase + bn0;
            if (gn < N && (k0 + bk0) < K) {
                float4 v = *reinterpret_cast<const float4*>(Bm + (long long)gn * ldb + (k0 + bk0));
                bR0 = v.x; bR1 = v.y; bR2 = v.z; bR3 = v.w;
            } else { bR0 = bR1 = bR2 = bR3 = 0.f; }
        } else {
            int gk = k0 + bk1;
            int gn = colBase + bn1;
            if (gk < K) {
                long long ro = (long long)gk * ldb;
                bR0 = (gn     < N) ? Bm[ro + gn]     : 0.f;
                bR1 = (gn + 1 < N) ? Bm[ro + gn + 1] : 0.f;
                bR2 = (gn + 2 < N) ? Bm[ro + gn + 2] : 0.f;
                bR3 = (gn + 3 < N) ? Bm[ro + gn + 3] : 0.f;
            } else { bR0 = bR1 = bR2 = bR3 = 0.f; }
        }
    };
    auto storeTile = [&](int buf) {
        As[buf][ak + 0][am] = aR0.x;
        As[buf][ak + 1][am] = aR0.y;
        As[buf][ak + 2][am] = aR0.z;
        As[buf][ak + 3][am] = aR0.w;
        As[buf][ak + 8][am]  = aR1.x;
        As[buf][ak + 9][am]  = aR1.y;
        As[buf][ak + 10][am] = aR1.z;
        As[buf][ak + 11][am] = aR1.w;
        if (b_kn == 0) {
            Bs[buf][bk0 + 0][bn0] = bR0;
            Bs[buf][bk0 + 1][bn0] = bR1;
            Bs[buf][bk0 + 2][bn0] = bR2;
            Bs[buf][bk0 + 3][bn0] = bR3;
        } else {
            Bs[buf][bk1][bn1 + 0] = bR0;
            Bs[buf][bk1][bn1 + 1] = bR1;
            Bs[buf][bk1][bn1 + 2] = bR2;
            Bs[buf][bk1][bn1 + 3] = bR3;
        }
    };

    if (!SP) {
        // zero my accT column (each thread touches only its own column)
        #pragma unroll
        for (int s = 0; s < 32; s++) accTs[s][t] = 0.f;
    }

    float accP[8][4] = {};   // current panel chains (hot registers)

    loadA(0); loadB(0);
    storeTile(0);
    __syncthreads();

    int cur = 0;
    int k0 = 0;
    while (k0 < K) {
        const int cs = (K - k0 < BK) ? (K - k0) : BK;   // 16, or 8 remainder
        const int kn = k0 + cs;
        const bool hasNext = kn < K;
        if (hasNext) { loadA(kn); loadB(kn); }

        // ascending k within panel; cs is 16 or 8
        #define KSTEP(kk)                                                        \
        {                                                                        \
            float4 a0 = *reinterpret_cast<const float4*>(&As[cur][kk][ty * 8]);  \
            float4 a1 = *reinterpret_cast<const float4*>(&As[cur][kk][ty * 8 + 4]);\
            float4 b  = *reinterpret_cast<const float4*>(&Bs[cur][kk][tx * 4]);  \
            float a_[8] = {a0.x, a0.y, a0.z, a0.w, a1.x, a1.y, a1.z, a1.w};      \
            float b_[4] = {b.x, b.y, b.z, b.w};                                  \
            _Pragma("unroll")                                                    \
            for (int i = 0; i < 8; i++)                                          \
                _Pragma("unroll")                                                \
                for (int j = 0; j < 4; j++)                                      \
                    accP[i][j] = fmaf(a_[i], b_[j], accP[i][j]);                 \
        }
        if (cs == BK) {
            #pragma unroll
            for (int k = 0; k < BK; k++) KSTEP(k)
        } else {
            #pragma unroll
            for (int k = 0; k < 8; k++) KSTEP(k)
        }
        #undef KSTEP

        // Eigen kc-panel boundary (kc % 16 == 0 -> always chunk-aligned)
        if (!SP) {
            if (((kn % kc) == 0) || !hasNext) {
                #pragma unroll
                for (int i = 0; i < 8; i++)
                    #pragma unroll
                    for (int j = 0; j < 4; j++) {
                        accTs[i * 4 + j][t] += accP[i][j];   // scalar IEEE add, same order
                        accP[i][j] = 0.f;
                    }
            }
        }

        if (hasNext) storeTile(cur ^ 1);
        __syncthreads();
        cur ^= 1;
        k0 = kn;
    }

    #pragma unroll
    for (int i = 0; i < 8; i++) {
        int gr = rowBase + ty * 8 + i;   // M % 128 == 0 -> always valid
        #pragma unroll
        for (int j = 0; j < 4; j++) {
            int gn = colBase + tx * 4 + j;
            if (gn >= N) continue;
            float v = alpha * (SP ? accP[i][j] : accTs[i * 4 + j][t]);
            if (bias) v += bias[gn];
            if (res)  v += res[(long long)gr * N + gn];
            if (spike) v = (v > thr) ? 1.0f : 0.0f;
            C[(long long)gr * N + gn] = v;
        }
    }
}

// row softmax over 512 columns; one block (256 threads) per row.
__global__ __launch_bounds__(256)
void softmax512_kernel(float* __restrict__ attn)
{
    long long row = blockIdx.x;
    float* p = attn + row * (long long)S_;
    int t = threadIdx.x;
    float v0 = p[t], v1 = p[t + 256];

    __shared__ float  redf[8];
    __shared__ double redd[8];

    float m = fmaxf(v0, v1);
    #pragma unroll
    for (int o = 16; o; o >>= 1) m = fmaxf(m, __shfl_xor_sync(0xffffffffu, m, o));
    if ((t & 31) == 0) redf[t >> 5] = m;
    __syncthreads();
    float mm = redf[0];
    #pragma unroll
    for (int i = 1; i < 8; i++) mm = fmaxf(mm, redf[i]);
    __syncthreads();

    float e0 = (float)exp((double)(v0 - mm));
    float e1 = (float)exp((double)(v1 - mm));

    double s = (double)e0 + (double)e1;
    #pragma unroll
    for (int o = 16; o; o >>= 1) s += __shfl_xor_sync(0xffffffffu, s, o);
    if ((t & 31) == 0) redd[t >> 5] = s;
    __syncthreads();
    double stot_d = 0.0;
    #pragma unroll
    for (int i = 0; i < 8; i++) stot_d += redd[i];
    float stot = (float)stot_d;

    p[t]       = e0 / stot;   // IEEE fp32 divide
    p[t + 256] = e1 / stot;
}

// final layer: cur3 = spk2 @ W3^T (K=200 < 320: single panel, ascending chain),
// + b3 last; spk3 = cur3>0.3; mem3 = cur3 - 0.3*spk3
__global__ __launch_bounds__(64)
void final_kernel(const float* __restrict__ spk2,
                  const float* __restrict__ W3,
                  const float* __restrict__ b3,
                  float* __restrict__ out)
{
    int r = blockIdx.x;
    __shared__ float row[DH2];
    for (int i = threadIdx.x; i < DH2; i += blockDim.x)
        row[i] = spk2[(long long)r * DH2 + i];
    __syncthreads();
    if (threadIdx.x < DOUT) {
        int o = threadIdx.x;
        float acc = 0.0f;
        for (int k = 0; k < DH2; k++)
            acc = fmaf(row[k], W3[o * DH2 + k], acc);
        acc += b3[o];
        float spk = (acc > 0.3f) ? 1.0f : 0.0f;
        out[(long long)r * DOUT + o] = spk;
        out[(long long)MROWS * DOUT + (long long)r * DOUT + o] = acc - spk * 0.3f;
    }
}

// ---------------- launch ----------------
extern "C" void kernel_launch(void* const* d_in, const int* in_sizes, int n_in,
                              void* d_out, int out_size)
{
    const float* x  = (const float*)d_in[0];
    const float* We = (const float*)d_in[1];
    const float* be = (const float*)d_in[2];
    const float* Wq = (const float*)d_in[3];
    const float* bq = (const float*)d_in[4];
    const float* Wk = (const float*)d_in[5];
    const float* bk = (const float*)d_in[6];
    const float* Wv = (const float*)d_in[7];
    const float* bv = (const float*)d_in[8];
    const float* W2 = (const float*)d_in[9];
    const float* b2 = (const float*)d_in[10];
    const float* W3 = (const float*)d_in[11];
    const float* b3 = (const float*)d_in[12];
    float* out = (float*)d_out;

    float *spk1, *QKb, *Vb, *attn, *attnout, *spk2, *Wqk, *bqk;
    cudaGetSymbolAddress((void**)&spk1,    d_spk1);
    cudaGetSymbolAddress((void**)&QKb,     d_QK);
    cudaGetSymbolAddress((void**)&Vb,      d_V);
    cudaGetSymbolAddress((void**)&attn,    d_attn);
    cudaGetSymbolAddress((void**)&attnout, d_attnout);
    cudaGetSymbolAddress((void**)&spk2,    d_spk2);
    cudaGetSymbolAddress((void**)&Wqk,     d_Wqk);
    cudaGetSymbolAddress((void**)&bqk,     d_bqk);

    // one-time side stream + fork/join events (host resources only; no device mem)
    static cudaStream_t s2 = nullptr;
    static cudaEvent_t  evFork = nullptr, evJoin = nullptr;
    if (!s2) {
        cudaStreamCreate(&s2);
        cudaEventCreateWithFlags(&evFork, cudaEventDisableTiming);
        cudaEventCreateWithFlags(&evJoin, cudaEventDisableTiming);
    }

    // 1) global max of x; pack Wq|Wk
    reset_kernel<<<1, 1>>>();
    reduce_max_kernel<<<512, 256>>>(x, MROWS * DIN);
    pack_qk_kernel<<<(DQK * DEMB + 255) / 256, 256>>>(Wq, Wk, bq, bk, Wqk, bqk);

    // 2) embed + LIF1 -> spk1 (K=784: panels 320,320,144)
    gemm_kernel<false><<<dim3((DEMB + BN - 1) / BN, MROWS / BM, 1), NT>>>(
        x, We, be, nullptr, spk1,
        MROWS, DEMB, DIN, DIN, DIN, KC_MAIN,
        0, 0, 0, 1.0f, 0, 1, 0.5f, 1);

    // fork: side stream runs QK -> scores -> softmax while main stream runs V
    cudaEventRecord(evFork, 0);
    cudaStreamWaitEvent(s2, evFork, 0);

    // 3a) [s2] QK fused (N=128, packed weights); K=600: panels 320,280
    gemm_kernel<false><<<dim3(2 * DQK / BN, MROWS / BM, 1), NT, 0, s2>>>(
        spk1, Wqk, bqk, nullptr, QKb,
        MROWS, 2 * DQK, DEMB, DEMB, DEMB, KC_MAIN,
        0, 0, 0, 1.0f, 0, 0, 0.f, 0);

    // 4a) [s2] scores = Q @ K^T * 1/8 (K=64: SINGLE PANEL specialization)
    gemm_kernel<true><<<dim3(S_ / BN, S_ / BM, B_), NT, 0, s2>>>(
        QKb, QKb + DQK, nullptr, nullptr, attn,
        S_, S_, DQK, 2 * DQK, 2 * DQK, KC_MAIN,
        (long long)S_ * 2 * DQK, (long long)S_ * 2 * DQK, (long long)S_ * S_,
        0.125f, 0, 0, 0.f, 0);

    // 5a) [s2] softmax rows
    softmax512_kernel<<<B_ * S_, 256, 0, s2>>>(attn);
    cudaEventRecord(evJoin, s2);

    // 3b) [main] V (K=600: panels 320,280) — runs concurrently with 3a-5a
    gemm_kernel<false><<<dim3((DEMB + BN - 1) / BN, MROWS / BM, 1), NT>>>(
        spk1, Wv, bv, nullptr, Vb,
        MROWS, DEMB, DEMB, DEMB, DEMB, KC_MAIN,
        0, 0, 0, 1.0f, 0, 0, 0.f, 0);

    // join: attn@V needs softmax (s2) + V (main)
    cudaStreamWaitEvent(0, evJoin, 0);

    // 6) attn_out = attn @ V + spk1 (K=512: panels 320,192); V is [K,N] per batch
    gemm_kernel<false><<<dim3((DEMB + BN - 1) / BN, S_ / BM, B_), NT>>>(
        attn, Vb, nullptr, spk1, attnout,
        S_, DEMB, S_, S_, DEMB, KC_MAIN,
        (long long)S_ * S_, (long long)S_ * DEMB, (long long)S_ * DEMB,
        1.0f, 1, 0, 0.f, 0);

    // 7) cur2 + LIF2 -> spk2 (K=600: panels 320,280)
    gemm_kernel<false><<<dim3((DH2 + BN - 1) / BN, MROWS / BM, 1), NT>>>(
        attnout, W2, b2, nullptr, spk2,
        MROWS, DH2, DEMB, DEMB, DEMB, KC_MAIN,
        0, 0, 0, 1.0f, 0, 1, 0.3f, 0);

    // 8) final layer -> (spk3, mem3)
    final_kernel<<<MROWS, 64>>>(spk2, W3, b3, out);

    (void)in_sizes; (void)n_in; (void)out_size;
}

// round 17
// speedup vs baseline: 1.3896x; 1.0994x over previous
#include <cuda_runtime.h>
#include <cuda_bf16.h>
#include <math.h>

// ---------------- problem dims ----------------
#define B_   64
#define S_   512
#define DIN  784
#define DEMB 600
#define DQK  64
#define DH2  200
#define DOUT 10
#define MROWS (B_*S_)   // 32768

// Eigen MT gebp K-panel size (confirmed bit-exact in R5): kc = 320
#define KC_MAIN 320

// ---------------- scratch (device globals: no allocation allowed) ----------------
__device__ unsigned int g_max_u;
static __device__ float d_spk1   [(size_t)MROWS*DEMB];
static __device__ float d_QK     [(size_t)MROWS*(2*DQK)];   // Q cols 0-63, K cols 64-127
static __device__ float d_V      [(size_t)MROWS*DEMB];
static __device__ float d_attn   [(size_t)B_*S_*S_];
static __device__ float d_attnout[(size_t)MROWS*DEMB];
static __device__ float d_spk2   [(size_t)MROWS*DH2];
static __device__ float d_WvT    [(size_t)DEMB*DEMB];       // WvT[k][n] = Wv[n][k]
static __device__ float d_WqkT   [(size_t)DEMB*(2*DQK)];    // WqkT[k][n] = (Wq|Wk)[n][k]
static __device__ float d_bqk    [2*DQK];

// ---------------- kernels ----------------
__global__ void reset_kernel() { g_max_u = 0u; }

__global__ void reduce_max_kernel(const float* __restrict__ x, int n) {
    float m = 0.f;
    for (int i = blockIdx.x * blockDim.x + threadIdx.x; i < n; i += gridDim.x * blockDim.x)
        m = fmaxf(m, x[i]);
    #pragma unroll
    for (int o = 16; o; o >>= 1) m = fmaxf(m, __shfl_xor_sync(0xffffffffu, m, o));
    if ((threadIdx.x & 31) == 0) atomicMax(&g_max_u, __float_as_uint(m)); // x >= 0
}

// WvT[k][n] = Wv[n][k]  (600x600)
__global__ void transposeV_kernel(const float* __restrict__ Wv, float* __restrict__ WvT) {
    int i = blockIdx.x * blockDim.x + threadIdx.x;
    if (i < DEMB * DEMB) {
        int k = i / DEMB, n = i % DEMB;
        WvT[i] = Wv[n * DEMB + k];
    }
}
// WqkT[k][n] = n<64 ? Wq[n][k] : Wk[n-64][k]  (600x128); also pack bqk
__global__ void transposeQK_kernel(const float* __restrict__ Wq, const float* __restrict__ Wk,
                                   const float* __restrict__ bq, const float* __restrict__ bk,
                                   float* __restrict__ WqkT, float* __restrict__ bqk) {
    int i = blockIdx.x * blockDim.x + threadIdx.x;
    if (i < DEMB * 2 * DQK) {
        int k = i / (2 * DQK), n = i % (2 * DQK);
        WqkT[i] = (n < DQK) ? Wq[n * DEMB + k] : Wk[(n - DQK) * DEMB + k];
    }
    if (i < DQK)        bqk[i] = bq[i];
    else if (i < 2*DQK) bqk[i] = bk[i - DQK];
}

// Sparse row-gather projection: out[row][n] = (sum_{k in spikes, k<320} Wt[k][n])
//                                           + (sum_{k in spikes, k>=320} Wt[k][n]) + bias[n]
// BIT-EXACT vs the dense gemm chain: fmaf(0,w,acc)==acc and fmaf(1,w,acc)==acc+w
// (exact product => FMA rounds identically to FADD); ascending-k order kept;
// two-phase sum == accT+=accP folds at the kc=320 panel boundary (K=600<2*320).
// spk: [MROWS][600] of exactly 0.0f/1.0f. One block per row.
__global__ void sparse_proj_kernel(const float* __restrict__ spk,
                                   const float* __restrict__ Wt,   // [600][Ncols]
                                   const float* __restrict__ bias, // [Ncols]
                                   float* __restrict__ out,        // [MROWS][Ncols]
                                   int Ncols)
{
    __shared__ int list[DEMB];
    __shared__ int cnts[2];
    const int row = blockIdx.x;
    const float* srow = spk + (long long)row * DEMB;
    const int t = threadIdx.x;

    if (t < 32) {
        int base = 0, base320 = 0;
        #pragma unroll
        for (int w = 0; w < 19; w++) {           // 600 = 18*32 + 24
            int k = w * 32 + t;
            bool p = (k < DEMB) && (srow[k] > 0.5f);
            unsigned m = __ballot_sync(0xffffffffu, p);
            if (w == 10) base320 = base;         // k = 320 boundary (10*32)
            if (p) list[base + __popc(m & ((1u << t) - 1u))] = k;
            base += __popc(m);
        }
        if (t == 0) { cnts[0] = base320; cnts[1] = base; }
    }
    __syncthreads();
    const int c1 = cnts[0], c2 = cnts[1];

    for (int n = t; n < Ncols; n += blockDim.x) {
        float a1 = 0.f, a2 = 0.f;
        for (int j = 0; j < c1; j++) a1 += Wt[(long long)list[j] * Ncols + n];  // panel 1, ascending
        for (int j = c1; j < c2; j++) a2 += Wt[(long long)list[j] * Ncols + n]; // panel 2, ascending
        float tot = a1;        // accT (=0) += accP(panel1)  -> exact
        tot += a2;             // accT += accP(panel2)
        out[(long long)row * Ncols + n] = tot + bias[n];   // alpha=1 exact, bias last
    }
}

// Tiled fp32 GEMM emulating Eigen gebp accumulation order (BIT-EXACT vs R5/R14):
//   per output: ascending-k fmaf chain (accP regs), folded into smem running
//   totals at kc=320 panel boundaries. SP=true: single-panel (K<=kc) keeps
//   totals in regs. A: [M,*] stride lda; B: b_kn==0 -> [N,*] ldb, b_kn==1 ->
//   [*,N] ldb. Batched via blockIdx.z (sA,sB,sC; res uses sC).
#define BM 128
#define BN 64
#define BK 16
#define NT 256
template<bool SP>
__global__ __launch_bounds__(NT, 3)
void gemm_kernel(const float* __restrict__ A,
                 const float* __restrict__ Bm,
                 const float* __restrict__ bias,
                 const float* __restrict__ res,
                 float* __restrict__ C,
                 int M, int N, int K, int lda, int ldb, int kc,
                 long long sA, long long sB, long long sC,
                 float alpha, int b_kn, int spike, float thr, int scaleA)
{
    __shared__ float As[2][BK][BM];
    __shared__ float Bs[2][BK][BN];
    __shared__ float accTs[SP ? 1 : 32][NT];

    long long bz = blockIdx.z;
    A  += bz * sA;
    Bm += bz * sB;
    C  += bz * sC;
    if (res) res += bz * sC;

    const int rowBase = blockIdx.y * BM;
    const int colBase = blockIdx.x * BN;
    const int t  = threadIdx.x;
    const int tx = t & 15;
    const int ty = t >> 4;

    float sc = 1.0f;
    if (scaleA) sc = (__uint_as_float(g_max_u) > 1.0f) ? (1.0f / 255.0f) : 1.0f;

    const int am = t >> 1;
    const int ak = (t & 1) * 4;
    const int bn0 = t >> 2;
    const int bk0 = (t & 3) * 4;
    const int bk1 = t >> 4;
    const int bn1 = (t & 15) * 4;

    float4 aR0, aR1;
    float  bR0, bR1, bR2, bR3;

    auto loadA = [&](int k0) {
        const float* base = A + (long long)(rowBase + am) * lda;
        if (k0 + ak < K) {
            aR0 = *reinterpret_cast<const float4*>(base + k0 + ak);
            aR0.x *= sc; aR0.y *= sc; aR0.z *= sc; aR0.w *= sc;
        } else aR0 = make_float4(0.f, 0.f, 0.f, 0.f);
        if (k0 + 8 + ak < K) {
            aR1 = *reinterpret_cast<const float4*>(base + k0 + 8 + ak);
            aR1.x *= sc; aR1.y *= sc; aR1.z *= sc; aR1.w *= sc;
        } else aR1 = make_float4(0.f, 0.f, 0.f, 0.f);
    };
    auto loadB = [&](int k0) {
        if (b_kn == 0) {
            int gn = colBase + bn0;
            if (gn < N && (k0 + bk0) < K) {
                float4 v = *reinterpret_cast<const float4*>(Bm + (long long)gn * ldb + (k0 + bk0));
                bR0 = v.x; bR1 = v.y; bR2 = v.z; bR3 = v.w;
            } else { bR0 = bR1 = bR2 = bR3 = 0.f; }
        } else {
            int gk = k0 + bk1;
            int gn = colBase + bn1;
            if (gk < K) {
                long long ro = (long long)gk * ldb;
                bR0 = (gn     < N) ? Bm[ro + gn]     : 0.f;
                bR1 = (gn + 1 < N) ? Bm[ro + gn + 1] : 0.f;
                bR2 = (gn + 2 < N) ? Bm[ro + gn + 2] : 0.f;
                bR3 = (gn + 3 < N) ? Bm[ro + gn + 3] : 0.f;
            } else { bR0 = bR1 = bR2 = bR3 = 0.f; }
        }
    };
    auto storeTile = [&](int buf) {
        As[buf][ak + 0][am] = aR0.x;
        As[buf][ak + 1][am] = aR0.y;
        As[buf][ak + 2][am] = aR0.z;
        As[buf][ak + 3][am] = aR0.w;
        As[buf][ak + 8][am]  = aR1.x;
        As[buf][ak + 9][am]  = aR1.y;
        As[buf][ak + 10][am] = aR1.z;
        As[buf][ak + 11][am] = aR1.w;
        if (b_kn == 0) {
            Bs[buf][bk0 + 0][bn0] = bR0;
            Bs[buf][bk0 + 1][bn0] = bR1;
            Bs[buf][bk0 + 2][bn0] = bR2;
            Bs[buf][bk0 + 3][bn0] = bR3;
        } else {
            Bs[buf][bk1][bn1 + 0] = bR0;
            Bs[buf][bk1][bn1 + 1] = bR1;
            Bs[buf][bk1][bn1 + 2] = bR2;
            Bs[buf][bk1][bn1 + 3] = bR3;
        }
    };

    if (!SP) {
        #pragma unroll
        for (int s = 0; s < 32; s++) accTs[s][t] = 0.f;
    }

    float accP[8][4] = {};

    loadA(0); loadB(0);
    storeTile(0);
    __syncthreads();

    int cur = 0;
    int k0 = 0;
    while (k0 < K) {
        const int cs = (K - k0 < BK) ? (K - k0) : BK;
        const int kn = k0 + cs;
        const bool hasNext = kn < K;
        if (hasNext) { loadA(kn); loadB(kn); }

        #define KSTEP(kk)                                                        \
        {                                                                        \
            float4 a0 = *reinterpret_cast<const float4*>(&As[cur][kk][ty * 8]);  \
            float4 a1 = *reinterpret_cast<const float4*>(&As[cur][kk][ty * 8 + 4]);\
            float4 b  = *reinterpret_cast<const float4*>(&Bs[cur][kk][tx * 4]);  \
            float a_[8] = {a0.x, a0.y, a0.z, a0.w, a1.x, a1.y, a1.z, a1.w};      \
            float b_[4] = {b.x, b.y, b.z, b.w};                                  \
            _Pragma("unroll")                                                    \
            for (int i = 0; i < 8; i++)                                          \
                _Pragma("unroll")                                                \
                for (int j = 0; j < 4; j++)                                      \
                    accP[i][j] = fmaf(a_[i], b_[j], accP[i][j]);                 \
        }
        if (cs == BK) {
            #pragma unroll
            for (int k = 0; k < BK; k++) KSTEP(k)
        } else {
            #pragma unroll
            for (int k = 0; k < 8; k++) KSTEP(k)
        }
        #undef KSTEP

        if (!SP) {
            if (((kn % kc) == 0) || !hasNext) {
                #pragma unroll
                for (int i = 0; i < 8; i++)
                    #pragma unroll
                    for (int j = 0; j < 4; j++) {
                        accTs[i * 4 + j][t] += accP[i][j];
                        accP[i][j] = 0.f;
                    }
            }
        }

        if (hasNext) storeTile(cur ^ 1);
        __syncthreads();
        cur ^= 1;
        k0 = kn;
    }

    #pragma unroll
    for (int i = 0; i < 8; i++) {
        int gr = rowBase + ty * 8 + i;
        #pragma unroll
        for (int j = 0; j < 4; j++) {
            int gn = colBase + tx * 4 + j;
            if (gn >= N) continue;
            float v = alpha * (SP ? accP[i][j] : accTs[i * 4 + j][t]);
            if (bias) v += bias[gn];
            if (res)  v += res[(long long)gr * N + gn];
            if (spike) v = (v > thr) ? 1.0f : 0.0f;
            C[(long long)gr * N + gn] = v;
        }
    }
}

// row softmax over 512 columns; one block (256 threads) per row.
__global__ __launch_bounds__(256)
void softmax512_kernel(float* __restrict__ attn)
{
    long long row = blockIdx.x;
    float* p = attn + row * (long long)S_;
    int t = threadIdx.x;
    float v0 = p[t], v1 = p[t + 256];

    __shared__ float  redf[8];
    __shared__ double redd[8];

    float m = fmaxf(v0, v1);
    #pragma unroll
    for (int o = 16; o; o >>= 1) m = fmaxf(m, __shfl_xor_sync(0xffffffffu, m, o));
    if ((t & 31) == 0) redf[t >> 5] = m;
    __syncthreads();
    float mm = redf[0];
    #pragma unroll
    for (int i = 1; i < 8; i++) mm = fmaxf(mm, redf[i]);
    __syncthreads();

    float e0 = (float)exp((double)(v0 - mm));
    float e1 = (float)exp((double)(v1 - mm));

    double s = (double)e0 + (double)e1;
    #pragma unroll
    for (int o = 16; o; o >>= 1) s += __shfl_xor_sync(0xffffffffu, s, o);
    if ((t & 31) == 0) redd[t >> 5] = s;
    __syncthreads();
    double stot_d = 0.0;
    #pragma unroll
    for (int i = 0; i < 8; i++) stot_d += redd[i];
    float stot = (float)stot_d;

    p[t]       = e0 / stot;   // IEEE fp32 divide
    p[t + 256] = e1 / stot;
}

// final layer: cur3 = spk2 @ W3^T + b3 last; spk3/mem3
__global__ __launch_bounds__(64)
void final_kernel(const float* __restrict__ spk2,
                  const float* __restrict__ W3,
                  const float* __restrict__ b3,
                  float* __restrict__ out)
{
    int r = blockIdx.x;
    __shared__ float row[DH2];
    for (int i = threadIdx.x; i < DH2; i += blockDim.x)
        row[i] = spk2[(long long)r * DH2 + i];
    __syncthreads();
    if (threadIdx.x < DOUT) {
        int o = threadIdx.x;
        float acc = 0.0f;
        for (int k = 0; k < DH2; k++)
            acc = fmaf(row[k], W3[o * DH2 + k], acc);
        acc += b3[o];
        float spk = (acc > 0.3f) ? 1.0f : 0.0f;
        out[(long long)r * DOUT + o] = spk;
        out[(long long)MROWS * DOUT + (long long)r * DOUT + o] = acc - spk * 0.3f;
    }
}

// ---------------- launch ----------------
extern "C" void kernel_launch(void* const* d_in, const int* in_sizes, int n_in,
                              void* d_out, int out_size)
{
    const float* x  = (const float*)d_in[0];
    const float* We = (const float*)d_in[1];
    const float* be = (const float*)d_in[2];
    const float* Wq = (const float*)d_in[3];
    const float* bq = (const float*)d_in[4];
    const float* Wk = (const float*)d_in[5];
    const float* bk = (const float*)d_in[6];
    const float* Wv = (const float*)d_in[7];
    const float* bv = (const float*)d_in[8];
    const float* W2 = (const float*)d_in[9];
    const float* b2 = (const float*)d_in[10];
    const float* W3 = (const float*)d_in[11];
    const float* b3 = (const float*)d_in[12];
    float* out = (float*)d_out;

    float *spk1, *QKb, *Vb, *attn, *attnout, *spk2, *WvT, *WqkT, *bqk;
    cudaGetSymbolAddress((void**)&spk1,    d_spk1);
    cudaGetSymbolAddress((void**)&QKb,     d_QK);
    cudaGetSymbolAddress((void**)&Vb,      d_V);
    cudaGetSymbolAddress((void**)&attn,    d_attn);
    cudaGetSymbolAddress((void**)&attnout, d_attnout);
    cudaGetSymbolAddress((void**)&spk2,    d_spk2);
    cudaGetSymbolAddress((void**)&WvT,     d_WvT);
    cudaGetSymbolAddress((void**)&WqkT,    d_WqkT);
    cudaGetSymbolAddress((void**)&bqk,     d_bqk);

    // one-time side stream + events (host resources only; no device mem)
    static cudaStream_t s2 = nullptr;
    static cudaEvent_t  evFork0 = nullptr, evT = nullptr, evFork = nullptr, evJoin = nullptr;
    if (!s2) {
        cudaStreamCreate(&s2);
        cudaEventCreateWithFlags(&evFork0, cudaEventDisableTiming);
        cudaEventCreateWithFlags(&evT,     cudaEventDisableTiming);
        cudaEventCreateWithFlags(&evFork,  cudaEventDisableTiming);
        cudaEventCreateWithFlags(&evJoin,  cudaEventDisableTiming);
    }

    // 1) main stream: reset + global max. Fork s2 FROM the captured stream
    //    (capture rule: side-stream work must originate from an event recorded
    //    on the origin stream), then s2 does the weight transposes.
    reset_kernel<<<1, 1>>>();
    cudaEventRecord(evFork0, 0);
    cudaStreamWaitEvent(s2, evFork0, 0);
    reduce_max_kernel<<<512, 256>>>(x, MROWS * DIN);
    transposeV_kernel<<<(DEMB * DEMB + 255) / 256, 256, 0, s2>>>(Wv, WvT);
    transposeQK_kernel<<<(DEMB * 2 * DQK + 255) / 256, 256, 0, s2>>>(Wq, Wk, bq, bk, WqkT, bqk);
    cudaEventRecord(evT, s2);

    // 2) embed + LIF1 -> spk1 (K=784: panels 320,320,144) — overlaps transposes
    gemm_kernel<false><<<dim3((DEMB + BN - 1) / BN, MROWS / BM, 1), NT>>>(
        x, We, be, nullptr, spk1,
        MROWS, DEMB, DIN, DIN, DIN, KC_MAIN,
        0, 0, 0, 1.0f, 0, 1, 0.5f, 1);

    // 3) sparse QK projection (needs spk1 + WqkT)
    cudaStreamWaitEvent(0, evT, 0);
    sparse_proj_kernel<<<MROWS, 128>>>(spk1, WqkT, bqk, QKb, 2 * DQK);

    // fork: s2 runs scores -> softmax while main runs sparse V
    cudaEventRecord(evFork, 0);
    cudaStreamWaitEvent(s2, evFork, 0);

    // 4a) [s2] scores = Q @ K^T * 1/8 (K=64: single-panel)
    gemm_kernel<true><<<dim3(S_ / BN, S_ / BM, B_), NT, 0, s2>>>(
        QKb, QKb + DQK, nullptr, nullptr, attn,
        S_, S_, DQK, 2 * DQK, 2 * DQK, KC_MAIN,
        (long long)S_ * 2 * DQK, (long long)S_ * 2 * DQK, (long long)S_ * S_,
        0.125f, 0, 0, 0.f, 0);

    // 5a) [s2] softmax rows
    softmax512_kernel<<<B_ * S_, 256, 0, s2>>>(attn);
    cudaEventRecord(evJoin, s2);

    // 3b) [main] sparse V projection — concurrent with 4a/5a
    sparse_proj_kernel<<<MROWS, 256>>>(spk1, WvT, bv, Vb, DEMB);

    // join: attn@V needs softmax (s2) + V (main)
    cudaStreamWaitEvent(0, evJoin, 0);

    // 6) attn_out = attn @ V + spk1 (K=512: panels 320,192); V is [K,N] per batch
    gemm_kernel<false><<<dim3((DEMB + BN - 1) / BN, S_ / BM, B_), NT>>>(
        attn, Vb, nullptr, spk1, attnout,
        S_, DEMB, S_, S_, DEMB, KC_MAIN,
        (long long)S_ * S_, (long long)S_ * DEMB, (long long)S_ * DEMB,
        1.0f, 1, 0, 0.f, 0);

    // 7) cur2 + LIF2 -> spk2 (K=600: panels 320,280)
    gemm_kernel<false><<<dim3((DH2 + BN - 1) / BN, MROWS / BM, 1), NT>>>(
        attnout, W2, b2, nullptr, spk2,
        MROWS, DH2, DEMB, DEMB, DEMB, KC_MAIN,
        0, 0, 0, 1.0f, 0, 1, 0.3f, 0);

    // 8) final layer -> (spk3, mem3)
    final_kernel<<<MROWS, 64>>>(spk2, W3, b3, out);

    (void)in_sizes; (void)n_in; (void)out_size;
}